// round 14
// baseline (speedup 1.0000x reference)
#include <cuda_runtime.h>
#include <cstdint>

// IoU is translation- and scale-invariant (reference grid offsets cancel),
// so compute in grid-relative units; typo y1_t = cy_t + w_t/2 preserved.

#define CELLS_PER_IMG 49
#define LAMBDA_COORD 5.0f
#define LAMBDA_NOOBJ 0.1f
#define EPSF 1e-12f

#define NTHREADS 256
#define NWARPS 8
#define TILE_CELLS 256
#define STAGES 2
#define PRE_TILE_FLOATS (TILE_CELLS * 10)
#define TRUE_TILE_FLOATS (TILE_CELLS * 5)
#define PRE_TILE_BYTES (PRE_TILE_FLOATS * 4)     // 10240
#define TRUE_TILE_BYTES (TRUE_TILE_FLOATS * 4)   // 5120
#define TILE_BYTES (PRE_TILE_BYTES + TRUE_TILE_BYTES)

__device__ float g_acc;   // zero-init in cubin; reset by finalize each launch

static __device__ __forceinline__ uint32_t smem_u32(const void* p) {
    return (uint32_t)__cvta_generic_to_shared(p);
}

static __device__ __forceinline__ void mbar_wait_parity(uint32_t m, int ph) {
    uint32_t done;
    asm volatile(
        "{\n\t.reg .pred p;\n\t"
        "mbarrier.try_wait.parity.acquire.cta.shared::cta.b64 p, [%1], %2;\n\t"
        "selp.b32 %0, 1, 0, p;\n\t}"
        : "=r"(done) : "r"(m), "r"((uint32_t)ph) : "memory");
    if (!done) {
        asm volatile(
            "{\n\t.reg .pred P1;\n\t"
            "WAIT_LOOP_%=:\n\t"
            "mbarrier.try_wait.parity.acquire.cta.shared::cta.b64 P1, [%0], %1, 0x989680;\n\t"
            "@P1 bra.uni WAIT_DONE_%=;\n\t"
            "bra.uni WAIT_LOOP_%=;\n\t"
            "WAIT_DONE_%=:\n\t}"
            :: "r"(m), "r"((uint32_t)ph) : "memory");
    }
}

static __device__ __forceinline__ void issue_tile_tma(
    uint32_t mbar, uint32_t dst_pre, uint32_t dst_true,
    const float* __restrict__ y_pre, const float* __restrict__ y_true, int tile) {
    asm volatile("mbarrier.arrive.expect_tx.shared.b64 _, [%0], %1;"
                 :: "r"(mbar), "r"((uint32_t)TILE_BYTES) : "memory");
    const void* srcp = y_pre + (size_t)tile * PRE_TILE_FLOATS;
    asm volatile("cp.async.bulk.shared::cluster.global.mbarrier::complete_tx::bytes "
                 "[%0], [%1], %2, [%3];"
                 :: "r"(dst_pre), "l"(srcp), "r"((uint32_t)PRE_TILE_BYTES), "r"(mbar)
                 : "memory");
    const void* srct = y_true + (size_t)tile * TRUE_TILE_FLOATS;
    asm volatile("cp.async.bulk.shared::cluster.global.mbarrier::complete_tx::bytes "
                 "[%0], [%1], %2, [%3];"
                 :: "r"(dst_true), "l"(srct), "r"((uint32_t)TRUE_TILE_BYTES), "r"(mbar)
                 : "memory");
}

__device__ __forceinline__ float iou_f(float bx, float by, float bw, float bh,
                                       float tx, float ty, float tw, float th) {
    float x0p = fmaf(-3.5f, bw, bx), x1p = fmaf(3.5f, bw, bx);
    float y0p = fmaf(-3.5f, bh, by), y1p = fmaf(3.5f, bh, by);
    float x0t = fmaf(-3.5f, tw, tx), x1t = fmaf(3.5f, tw, tx);
    float y0t = fmaf(-3.5f, th, ty);
    float y1t = fmaf(3.5f, tw, ty);   // TYPO kept from reference: uses w_t
    float ux0 = fmaxf(x0p, x0t);
    float ux1 = fminf(x1p, x1t);
    float uy0 = fmaxf(y0p, y0t);
    float uy1 = fminf(y1p, y1t);
    bool valid = (ux0 < ux1) && (uy0 < uy1);
    float area_u = (ux1 - ux0) * (uy1 - uy0);
    float area_p = (49.0f * bw) * bh;
    float area_t = (7.0f * tw) * (y1t - y0t);
    float res = __fdividef(area_u, area_p + area_t - area_u + EPSF);
    return valid ? res : 0.0f;
}

__device__ __forceinline__ float cell_loss(float p0, float p1, float p2, float p3, float p4,
                                           float p5, float p6, float p7, float p8, float p9,
                                           float t0, float t1, float t2, float t3, float t4) {
    float iou0 = iou_f(p0, p1, p2, p3, t0, t1, t2, t3);
    float iou1 = iou_f(p5, p6, p7, p8, t0, t1, t2, t3);
    bool obj = (t4 == 1.0f);
    bool c0 = iou0 > iou1;
    float local;
    if (obj) {
        float conf_pre = c0 ? p4 : p9;
        float conf_true = c0 ? iou0 : iou1;
        float dc = conf_pre - conf_true;
        local = dc * dc;
        float dx = (c0 ? p0 : p5) - t0;
        float dy = (c0 ? p1 : p6) - t1;
        local += LAMBDA_COORD * (dx * dx + dy * dy);
        float wb = fmaxf(c0 ? p2 : p7, EPSF);
        float hb = fmaxf(c0 ? p3 : p8, EPSF);
        float wt = fmaxf(t2, EPSF);
        float ht = fmaxf(t3, EPSF);
        float dw = sqrtf(wb) - sqrtf(wt);
        float dh = sqrtf(hb) - sqrtf(ht);
        local += LAMBDA_COORD * (dw * dw + dh * dh);
    } else {
        local = LAMBDA_NOOBJ * (p4 * p4 + p9 * p9);
    }
    return local;
}

__global__ void __launch_bounds__(NTHREADS)
yolo_loss_main(const float* __restrict__ y_pre,
               const float* __restrict__ y_true,
               int n_cells, int n_tiles_total, int full_tiles, float inv_b) {
    __shared__ __align__(16) float s_pre[STAGES][PRE_TILE_FLOATS];
    __shared__ __align__(16) float s_true[STAGES][TRUE_TILE_FLOATS];
    __shared__ __align__(8) uint64_t mbar[STAGES];

    int tid = threadIdx.x;
    int G = gridDim.x;
    int b = blockIdx.x;

    if (tid == 0) {
        #pragma unroll
        for (int s = 0; s < STAGES; s++) {
            uint32_t m = smem_u32(&mbar[s]);
            asm volatile("mbarrier.init.shared.b64 [%0], %1;" :: "r"(m), "r"(1u) : "memory");
        }
        asm volatile("fence.proxy.async.shared::cta;" ::: "memory");
    }
    __syncthreads();

    // Prologue: issue TMA for the first STAGES tiles of this block's sequence.
    if (tid == 0) {
        #pragma unroll
        for (int s = 0; s < STAGES; s++) {
            int tile = b + s * G;
            if (tile < full_tiles)
                issue_tile_tma(smem_u32(&mbar[s]),
                               smem_u32(&s_pre[s][0]), smem_u32(&s_true[s][0]),
                               y_pre, y_true, tile);
        }
    }

    float acc = 0.0f;
    int ph0 = 0, ph1 = 0;   // per-buffer mbarrier phase

    for (int i = 0;; i++) {
        int tile = b + i * G;
        if (tile >= n_tiles_total) break;
        int buf = i & 1;

        if (tile < full_tiles) {
            uint32_t m = smem_u32(&mbar[buf]);
            int ph = buf ? ph1 : ph0;
            mbar_wait_parity(m, ph);
            if (buf) ph1 ^= 1; else ph0 ^= 1;

            // per-cell reads from smem: float2 x5 (2-way conflicts max),
            // y_true scalars (stride 5 -> conflict-free)
            const float2* sp2 = (const float2*)&s_pre[buf][tid * 10];
            float2 p01 = sp2[0], p23 = sp2[1], p45 = sp2[2], p67 = sp2[3], p89 = sp2[4];
            const float* st = &s_true[buf][tid * 5];
            acc += cell_loss(p01.x, p01.y, p23.x, p23.y, p45.x,
                             p45.y, p67.x, p67.y, p89.x, p89.y,
                             st[0], st[1], st[2], st[3], st[4]);
        } else {
            // partial tail tile (no TMA issued): direct global loads
            int idx = tile * TILE_CELLS + tid;
            if (idx < n_cells) {
                const float2* p = (const float2*)(y_pre + (size_t)idx * 10);
                float2 p01 = p[0], p23 = p[1], p45 = p[2], p67 = p[3], p89 = p[4];
                const float* t = y_true + (size_t)idx * 5;
                acc += cell_loss(p01.x, p01.y, p23.x, p23.y, p45.x,
                                 p45.y, p67.x, p67.y, p89.x, p89.y,
                                 t[0], t[1], t[2], t[3], t[4]);
            }
        }

        __syncthreads();   // all lanes done reading buf before refill

        int next_tile = b + (i + STAGES) * G;
        if (tid == 0 && next_tile < full_tiles)
            issue_tile_tma(smem_u32(&mbar[buf]),
                           smem_u32(&s_pre[buf][0]), smem_u32(&s_true[buf][0]),
                           y_pre, y_true, next_tile);
    }

    // ---- block reduction (fp32) ----
    #pragma unroll
    for (int off = 16; off > 0; off >>= 1)
        acc += __shfl_down_sync(0xFFFFFFFFu, acc, off);

    __shared__ float warp_sums[NWARPS];
    int lane = tid & 31;
    int wid = tid >> 5;
    if (lane == 0) warp_sums[wid] = acc;
    __syncthreads();

    if (wid == 0) {
        float v = (lane < NWARPS) ? warp_sums[lane] : 0.0f;
        #pragma unroll
        for (int off = 4; off > 0; off >>= 1)
            v += __shfl_down_sync(0xFFFFFFFFu, v, off);
        if (lane == 0)
            atomicAdd(&g_acc, v * inv_b);   // fire-and-forget RED.f32, pre-scaled
    }
}

__global__ void finalize_kernel(float* __restrict__ out) {
    // PDL: resident during the main grid; parks until main completes
    // (completion implies visibility of all REDs).
    asm volatile("griddepcontrol.wait;" ::: "memory");
    out[0] = g_acc;
    g_acc = 0.0f;   // re-arm accumulator for next graph replay
}

extern "C" void kernel_launch(void* const* d_in, const int* in_sizes, int n_in,
                              void* d_out, int out_size) {
    const float* y_pre = (const float*)d_in[0];
    const float* y_true = (const float*)d_in[1];
    float* out = (float*)d_out;

    int n_cells = in_sizes[1] / 5;               // B * 49
    int B = n_cells / CELLS_PER_IMG;
    float inv_b = 1.0f / (float)B;

    int n_tiles_total = (n_cells + TILE_CELLS - 1) / TILE_CELLS;
    int full_tiles = n_cells / TILE_CELLS;

    int grid = 148 * 6;    // ~6 blocks/SM (smem 30.8KB/block)
    if (grid > n_tiles_total) grid = n_tiles_total;

    yolo_loss_main<<<grid, NTHREADS>>>(y_pre, y_true, n_cells,
                                       n_tiles_total, full_tiles, inv_b);

    // PDL epilogue: parks during main, wakes at completion.
    cudaLaunchConfig_t cfg = {};
    cfg.gridDim = dim3(1, 1, 1);
    cfg.blockDim = dim3(1, 1, 1);
    cfg.dynamicSmemBytes = 0;
    cfg.stream = 0;
    cudaLaunchAttribute attrs[1];
    attrs[0].id = cudaLaunchAttributeProgrammaticStreamSerialization;
    attrs[0].val.programmaticStreamSerializationAllowed = 1;
    cfg.attrs = attrs;
    cfg.numAttrs = 1;
    cudaLaunchKernelEx(&cfg, finalize_kernel, out);
}

// round 15
// speedup vs baseline: 1.0175x; 1.0175x over previous
#include <cuda_runtime.h>

// IoU is translation- and scale-invariant (reference grid offsets cancel),
// so compute in grid-relative units; typo y1_t = cy_t + w_t/2 preserved.

#define CELLS_PER_IMG 49
#define LAMBDA_COORD 5.0f
#define LAMBDA_NOOBJ 0.1f
#define EPSF 1e-12f

#define NTHREADS 256
#define NWARPS (NTHREADS / 32)

__device__ double g_acc;   // zero-init in cubin; reset by finalize each launch

__device__ __forceinline__ float iou_f(float bx, float by, float bw, float bh,
                                       float tx, float ty, float tw, float th) {
    float x0p = fmaf(-3.5f, bw, bx), x1p = fmaf(3.5f, bw, bx);
    float y0p = fmaf(-3.5f, bh, by), y1p = fmaf(3.5f, bh, by);
    float x0t = fmaf(-3.5f, tw, tx), x1t = fmaf(3.5f, tw, tx);
    float y0t = fmaf(-3.5f, th, ty);
    float y1t = fmaf(3.5f, tw, ty);   // TYPO kept from reference: uses w_t
    float ux0 = fmaxf(x0p, x0t);
    float ux1 = fminf(x1p, x1t);
    float uy0 = fmaxf(y0p, y0t);
    float uy1 = fminf(y1p, y1t);
    bool valid = (ux0 < ux1) && (uy0 < uy1);
    float area_u = (ux1 - ux0) * (uy1 - uy0);
    float area_p = (49.0f * bw) * bh;
    float area_t = (7.0f * tw) * (y1t - y0t);
    float res = __fdividef(area_u, area_p + area_t - area_u + EPSF);
    return valid ? res : 0.0f;
}

__global__ void __launch_bounds__(NTHREADS)
yolo_loss_main(const float* __restrict__ y_pre,
               const float* __restrict__ y_true,
               int n_cells) {
    int tid = threadIdx.x;
    int idx = blockIdx.x * NTHREADS + tid;

    float local = 0.0f;
    if (idx < n_cells) {
        // y_pre cell: 10 floats, 40B stride -> 8B aligned -> float2 loads.
        // Streaming (evict-first) hints: data is touched exactly once.
        const float2* p = (const float2*)(y_pre + (size_t)idx * 10);
        float2 p01 = __ldcs(p + 0);
        float2 p23 = __ldcs(p + 1);
        float2 p45 = __ldcs(p + 2);
        float2 p67 = __ldcs(p + 3);
        float2 p89 = __ldcs(p + 4);

        const float* t = y_true + (size_t)idx * 5;
        float t0 = __ldcs(t + 0), t1 = __ldcs(t + 1), t2 = __ldcs(t + 2),
              t3 = __ldcs(t + 3), t4 = __ldcs(t + 4);

        float iou0 = iou_f(p01.x, p01.y, p23.x, p23.y, t0, t1, t2, t3);
        float iou1 = iou_f(p45.y, p67.x, p67.y, p89.x, t0, t1, t2, t3);

        bool obj = (t4 == 1.0f);
        bool c0 = iou0 > iou1;

        if (obj) {
            float conf_pre = c0 ? p45.x : p89.y;
            float conf_true = c0 ? iou0 : iou1;
            float dc = conf_pre - conf_true;
            local = dc * dc;
            float dx = (c0 ? p01.x : p45.y) - t0;
            float dy = (c0 ? p01.y : p67.x) - t1;
            local += LAMBDA_COORD * (dx * dx + dy * dy);
            float wb = fmaxf(c0 ? p23.x : p67.y, EPSF);
            float hb = fmaxf(c0 ? p23.y : p89.x, EPSF);
            float wt = fmaxf(t2, EPSF);
            float ht = fmaxf(t3, EPSF);
            float dw = sqrtf(wb) - sqrtf(wt);
            float dh = sqrtf(hb) - sqrtf(ht);
            local += LAMBDA_COORD * (dw * dw + dh * dh);
        } else {
            local = LAMBDA_NOOBJ * (p45.x * p45.x + p89.y * p89.y);
        }
    }

    // ---- block reduction (fp32) ----
    #pragma unroll
    for (int off = 16; off > 0; off >>= 1)
        local += __shfl_down_sync(0xFFFFFFFFu, local, off);

    __shared__ float warp_sums[NWARPS];
    int lane = tid & 31;
    int wid = tid >> 5;
    if (lane == 0) warp_sums[wid] = local;
    __syncthreads();

    if (wid == 0) {
        float v = (lane < NWARPS) ? warp_sums[lane] : 0.0f;
        #pragma unroll
        for (int off = 4; off > 0; off >>= 1)
            v += __shfl_down_sync(0xFFFFFFFFu, v, off);
        if (lane == 0)
            atomicAdd(&g_acc, (double)v);   // fire-and-forget RED.f64; no fence
    }
}

__global__ void finalize_kernel(float* __restrict__ out, float inv_b) {
    // PDL: resident during the main grid; parks until main completes
    // (completion implies visibility of all REDs).
    asm volatile("griddepcontrol.wait;" ::: "memory");
    out[0] = (float)(g_acc * (double)inv_b);
    g_acc = 0.0;   // re-arm accumulator for next graph replay
}

extern "C" void kernel_launch(void* const* d_in, const int* in_sizes, int n_in,
                              void* d_out, int out_size) {
    const float* y_pre = (const float*)d_in[0];
    const float* y_true = (const float*)d_in[1];
    float* out = (float*)d_out;

    int n_cells = in_sizes[1] / 5;               // B * 49
    int B = n_cells / CELLS_PER_IMG;
    float inv_b = 1.0f / (float)B;

    int grid = (n_cells + NTHREADS - 1) / NTHREADS;
    yolo_loss_main<<<grid, NTHREADS>>>(y_pre, y_true, n_cells);

    // PDL epilogue: parks during main, wakes at completion (~0.6us effective).
    cudaLaunchConfig_t cfg = {};
    cfg.gridDim = dim3(1, 1, 1);
    cfg.blockDim = dim3(1, 1, 1);
    cfg.dynamicSmemBytes = 0;
    cfg.stream = 0;
    cudaLaunchAttribute attrs[1];
    attrs[0].id = cudaLaunchAttributeProgrammaticStreamSerialization;
    attrs[0].val.programmaticStreamSerializationAllowed = 1;
    cfg.attrs = attrs;
    cfg.numAttrs = 1;
    cudaLaunchKernelEx(&cfg, finalize_kernel, out, inv_b);
}

// round 16
// speedup vs baseline: 1.0494x; 1.0314x over previous
#include <cuda_runtime.h>

// IoU is translation- and scale-invariant (reference grid offsets cancel),
// so compute in grid-relative units; typo y1_t = cy_t + w_t/2 preserved.

#define CELLS_PER_IMG 49
#define LAMBDA_COORD 5.0f
#define LAMBDA_NOOBJ 0.1f
#define EPSF 1e-12f

#define NTHREADS 256
#define NWARPS (NTHREADS / 32)

__device__ double g_acc;   // zero-init in cubin; reset by finalize each launch

__device__ __forceinline__ float iou_f(float bx, float by, float bw, float bh,
                                       float tx, float ty, float tw, float th) {
    float x0p = fmaf(-3.5f, bw, bx), x1p = fmaf(3.5f, bw, bx);
    float y0p = fmaf(-3.5f, bh, by), y1p = fmaf(3.5f, bh, by);
    float x0t = fmaf(-3.5f, tw, tx), x1t = fmaf(3.5f, tw, tx);
    float y0t = fmaf(-3.5f, th, ty);
    float y1t = fmaf(3.5f, tw, ty);   // TYPO kept from reference: uses w_t
    float ux0 = fmaxf(x0p, x0t);
    float ux1 = fminf(x1p, x1t);
    float uy0 = fmaxf(y0p, y0t);
    float uy1 = fminf(y1p, y1t);
    bool valid = (ux0 < ux1) && (uy0 < uy1);
    float area_u = (ux1 - ux0) * (uy1 - uy0);
    float area_p = (49.0f * bw) * bh;
    float area_t = (7.0f * tw) * (y1t - y0t);
    float res = __fdividef(area_u, area_p + area_t - area_u + EPSF);
    return valid ? res : 0.0f;
}

__global__ void __launch_bounds__(NTHREADS)
yolo_loss_main(const float* __restrict__ y_pre,
               const float* __restrict__ y_true,
               int n_cells) {
    int tid = threadIdx.x;
    int idx = blockIdx.x * NTHREADS + tid;

    float local = 0.0f;
    if (idx < n_cells) {
        // y_pre cell: 10 floats, 40B stride -> 8B aligned -> float2 loads
        const float2* p = (const float2*)(y_pre + (size_t)idx * 10);
        float2 p01 = p[0];
        float2 p23 = p[1];
        float2 p45 = p[2];
        float2 p67 = p[3];
        float2 p89 = p[4];

        const float* t = y_true + (size_t)idx * 5;
        float t0 = t[0], t1 = t[1], t2 = t[2], t3 = t[3], t4 = t[4];

        float iou0 = iou_f(p01.x, p01.y, p23.x, p23.y, t0, t1, t2, t3);
        float iou1 = iou_f(p45.y, p67.x, p67.y, p89.x, t0, t1, t2, t3);

        bool obj = (t4 == 1.0f);
        bool c0 = iou0 > iou1;

        if (obj) {
            float conf_pre = c0 ? p45.x : p89.y;
            float conf_true = c0 ? iou0 : iou1;
            float dc = conf_pre - conf_true;
            local = dc * dc;
            float dx = (c0 ? p01.x : p45.y) - t0;
            float dy = (c0 ? p01.y : p67.x) - t1;
            local += LAMBDA_COORD * (dx * dx + dy * dy);
            float wb = fmaxf(c0 ? p23.x : p67.y, EPSF);
            float hb = fmaxf(c0 ? p23.y : p89.x, EPSF);
            float wt = fmaxf(t2, EPSF);
            float ht = fmaxf(t3, EPSF);
            float dw = sqrtf(wb) - sqrtf(wt);
            float dh = sqrtf(hb) - sqrtf(ht);
            local += LAMBDA_COORD * (dw * dw + dh * dh);
        } else {
            local = LAMBDA_NOOBJ * (p45.x * p45.x + p89.y * p89.y);
        }
    }

    // ---- block reduction (fp32) ----
    #pragma unroll
    for (int off = 16; off > 0; off >>= 1)
        local += __shfl_down_sync(0xFFFFFFFFu, local, off);

    __shared__ float warp_sums[NWARPS];
    int lane = tid & 31;
    int wid = tid >> 5;
    if (lane == 0) warp_sums[wid] = local;
    __syncthreads();

    if (wid == 0) {
        float v = (lane < NWARPS) ? warp_sums[lane] : 0.0f;
        #pragma unroll
        for (int off = 4; off > 0; off >>= 1)
            v += __shfl_down_sync(0xFFFFFFFFu, v, off);
        if (lane == 0)
            atomicAdd(&g_acc, (double)v);   // fire-and-forget RED.f64; no fence
    }
}

__global__ void finalize_kernel(float* __restrict__ out, float inv_b) {
    // PDL: resident during the main grid; parks until main completes
    // (completion implies visibility of all REDs).
    asm volatile("griddepcontrol.wait;" ::: "memory");
    out[0] = (float)(g_acc * (double)inv_b);
    g_acc = 0.0;   // re-arm accumulator for next graph replay
}

extern "C" void kernel_launch(void* const* d_in, const int* in_sizes, int n_in,
                              void* d_out, int out_size) {
    const float* y_pre = (const float*)d_in[0];
    const float* y_true = (const float*)d_in[1];
    float* out = (float*)d_out;

    int n_cells = in_sizes[1] / 5;               // B * 49
    int B = n_cells / CELLS_PER_IMG;
    float inv_b = 1.0f / (float)B;

    int grid = (n_cells + NTHREADS - 1) / NTHREADS;
    yolo_loss_main<<<grid, NTHREADS>>>(y_pre, y_true, n_cells);

    // PDL epilogue: parks during main, wakes at completion (~0.6us effective).
    cudaLaunchConfig_t cfg = {};
    cfg.gridDim = dim3(1, 1, 1);
    cfg.blockDim = dim3(1, 1, 1);
    cfg.dynamicSmemBytes = 0;
    cfg.stream = 0;
    cudaLaunchAttribute attrs[1];
    attrs[0].id = cudaLaunchAttributeProgrammaticStreamSerialization;
    attrs[0].val.programmaticStreamSerializationAllowed = 1;
    cfg.attrs = attrs;
    cfg.numAttrs = 1;
    cudaLaunchKernelEx(&cfg, finalize_kernel, out, inv_b);
}